// round 12
// baseline (speedup 1.0000x reference)
#include <cuda_runtime.h>
#include <cuda_bf16.h>
#include <cstdint>

#define NTHREADS 256

// ---- smem: weights only (bf16-element offsets) ----
#define XSTR  136
#define ASTR  72
#define O_W2H 0
#define O_W2L (32 * XSTR)
#define O_WFH (2 * 32 * XSTR)
#define O_WFL (O_WFH + 128 * ASTR)
#define SM_ELEMS (O_WFL + 128 * ASTR)
#define O_BIAS (SM_ELEMS * 2)          // bytes: b2[32]f32 then bf[128]f32
#define O_SCR  (O_BIAS + 4 * (32 + 128))
#define SM_BYTES (O_SCR + 8 * 64 * 4)  // + per-warp o1 scratch (slow path)

typedef unsigned u32;

static __device__ __forceinline__ u32 s2u(const void* p) {
    u32 a;
    asm("{ .reg .u64 t; cvta.to.shared.u64 t, %1; cvt.u32.u64 %0, t; }" : "=r"(a) : "l"(p));
    return a;
}
static __device__ __forceinline__ void bfsplit(float v, __nv_bfloat16& h, __nv_bfloat16& l) {
    h = __float2bfloat16(v);
    l = __float2bfloat16(v - __bfloat162float(h));
}
// (a,b) -> packed bf16x2 hi (RN) + packed bf16x2 lo (residual)
static __device__ __forceinline__ void packhl(float a, float b, u32& h, u32& l) {
    asm("cvt.rn.bf16x2.f32 %0, %1, %2;" : "=r"(h) : "f"(b), "f"(a));
    float ra = a - __uint_as_float(h << 16);
    float rb = b - __uint_as_float(h & 0xffff0000u);
    asm("cvt.rn.bf16x2.f32 %0, %1, %2;" : "=r"(l) : "f"(rb), "f"(ra));
}
static __device__ __forceinline__ void ldmx4(u32 a[4], u32 addr) {
    asm volatile("ldmatrix.sync.aligned.m8n8.x4.shared.b16 {%0,%1,%2,%3}, [%4];"
                 : "=r"(a[0]), "=r"(a[1]), "=r"(a[2]), "=r"(a[3]) : "r"(addr));
}
static __device__ __forceinline__ void mmabf(float c[4], const u32 a[4], u32 b0, u32 b1) {
    asm volatile("mma.sync.aligned.m16n8k16.row.col.f32.bf16.bf16.f32 "
                 "{%0,%1,%2,%3}, {%4,%5,%6,%7}, {%8,%9}, {%0,%1,%2,%3};"
                 : "+f"(c[0]), "+f"(c[1]), "+f"(c[2]), "+f"(c[3])
                 : "r"(a[0]), "r"(a[1]), "r"(a[2]), "r"(a[3]), "r"(b0), "r"(b1));
}

__global__ void __launch_bounds__(NTHREADS, 2)
dynlayer_mma(const float* __restrict__ X,  const float* __restrict__ W1,
             const float* __restrict__ b1, const float* __restrict__ W2,
             const float* __restrict__ b2, const float* __restrict__ Wf,
             const float* __restrict__ bf, float* __restrict__ out, int nrows)
{
    extern __shared__ char smraw[];
    __nv_bfloat16* sh = (__nv_bfloat16*)smraw;
    float* b2s = (float*)(smraw + O_BIAS);
    float* bfs = b2s + 32;
    float* scr = (float*)(smraw + O_SCR);
    const u32 sb = s2u(smraw);
    const int tid = threadIdx.x, wid = tid >> 5, lane = tid & 31;

    // ---- stage weights (bf16 hi/lo, padded row-major) + biases ----
    for (int i = tid; i < 32 * 128; i += NTHREADS) {
        int u = i >> 7, k = i & 127; __nv_bfloat16 h, l; bfsplit(W2[i], h, l);
        sh[O_W2H + u * XSTR + k] = h; sh[O_W2L + u * XSTR + k] = l;
    }
    for (int i = tid; i < 128 * 64; i += NTHREADS) {
        int n = i >> 6, k = i & 63; __nv_bfloat16 h, l; bfsplit(Wf[i], h, l);
        sh[O_WFH + n * ASTR + k] = h; sh[O_WFL + n * ASTR + k] = l;
    }
    if (tid < 32)  b2s[tid] = b2[tid];
    if (tid < 128) bfs[tid] = bf[tid];
    __syncthreads();

    const int q  = lane >> 2;
    const int c2 = (lane & 3) * 2;

    const int brow  = ((lane >> 4) & 1) * 8 + (lane & 7);
    const int bcolh = ((lane >> 3) & 1) * 8;
    const u32 w2h = sb + (u32)((O_W2H + brow * XSTR + bcolh) * 2);
    const u32 w2l = sb + (u32)((O_W2L + brow * XSTR + bcolh) * 2);
    const u32 wfh = sb + (u32)((O_WFH + brow * ASTR + bcolh) * 2);
    const u32 wfl = sb + (u32)((O_WFL + brow * ASTR + bcolh) * 2);

    float2 b2c[4];
    #pragma unroll
    for (int nb = 0; nb < 4; nb++)
        b2c[nb] = *reinterpret_cast<const float2*>(b2s + nb * 8 + c2);

    const int ntiles = nrows >> 7;      // 128 rows per CTA-tile, 16 per warp
    const int stride = gridDim.x;
    const long rowoff = (long)(wid * 16 + q) * 128;

    // ---- prologue: prefetch half0 of the first tile ----
    float2 xf0[4][4], xf1[4][4];
    {
        const float* p0 = X + ((long)blockIdx.x << 7) * 128 + rowoff;
        #pragma unroll
        for (int kb = 0; kb < 4; kb++) {
            const int col0 = kb * 16 + c2;
            xf0[kb][0] = *reinterpret_cast<const float2*>(p0 + col0);
            xf0[kb][1] = *reinterpret_cast<const float2*>(p0 + 8 * 128 + col0);
            xf0[kb][2] = *reinterpret_cast<const float2*>(p0 + col0 + 8);
            xf0[kb][3] = *reinterpret_cast<const float2*>(p0 + 8 * 128 + col0 + 8);
        }
    }

    for (int t = blockIdx.x; t < ntiles; t += stride) {
        const long rw = ((long)t << 7) + wid * 16;
        const float* xr0 = X + rw * 128 + (long)q * 128;
        const float* xr1 = xr0 + 8 * 128;
        const bool has_next = (t + stride) < ntiles;
        const float* nxt = X + (((long)(t + stride)) << 7) * 128 + rowoff;

        // L2 prefetch of next tile's slab
        if (has_next) {
            const char* p = (const char*)nxt - rowoff * 4 + (long)wid * 16 * 512 + lane * 256;
            asm volatile("prefetch.global.L2 [%0];" :: "l"(p));
        }

        // issue half1 loads now (latency hidden behind GEMM1-half0)
        #pragma unroll
        for (int kb = 0; kb < 4; kb++) {
            const int col0 = (4 + kb) * 16 + c2;
            xf1[kb][0] = *reinterpret_cast<const float2*>(xr0 + col0);
            xf1[kb][1] = *reinterpret_cast<const float2*>(xr1 + col0);
            xf1[kb][2] = *reinterpret_cast<const float2*>(xr0 + col0 + 8);
            xf1[kb][3] = *reinterpret_cast<const float2*>(xr1 + col0 + 8);
        }

        float s1 = 0.f, s2 = 0.f;
        float accA[4][4], accB[4][4];
        #pragma unroll
        for (int nb = 0; nb < 4; nb++)
            #pragma unroll
            for (int j = 0; j < 4; j++) { accA[nb][j] = 0.f; accB[nb][j] = 0.f; }

        // ---- GEMM1 on half0 (xf0 preloaded last iteration) ----
        #pragma unroll
        for (int kb = 0; kb < 4; kb++) {
            s1 += fabsf(xf0[kb][0].x) + fabsf(xf0[kb][0].y) + fabsf(xf0[kb][2].x) + fabsf(xf0[kb][2].y);
            s2 += fabsf(xf0[kb][1].x) + fabsf(xf0[kb][1].y) + fabsf(xf0[kb][3].x) + fabsf(xf0[kb][3].y);
            u32 ah[4], al[4];
            #pragma unroll
            for (int j = 0; j < 4; j++) packhl(xf0[kb][j].x, xf0[kb][j].y, ah[j], al[j]);
            #pragma unroll
            for (int nbp = 0; nbp < 2; nbp++) {
                const u32 off = (u32)((nbp * 16 * XSTR + kb * 16) * 2);
                u32 bh[4], bl[4];
                ldmx4(bh, w2h + off);
                ldmx4(bl, w2l + off);
                mmabf(accA[2*nbp],   ah, bh[0], bh[1]);
                mmabf(accB[2*nbp],   ah, bl[0], bl[1]);
                mmabf(accB[2*nbp],   al, bh[0], bh[1]);
                mmabf(accA[2*nbp+1], ah, bh[2], bh[3]);
                mmabf(accB[2*nbp+1], ah, bl[2], bl[3]);
                mmabf(accB[2*nbp+1], al, bh[2], bh[3]);
            }
        }

        // xf0 dead -> prefetch NEXT tile's half0 (flies during GEMM1-half1 + GEMM2)
        if (has_next) {
            #pragma unroll
            for (int kb = 0; kb < 4; kb++) {
                const int col0 = kb * 16 + c2;
                xf0[kb][0] = *reinterpret_cast<const float2*>(nxt + col0);
                xf0[kb][1] = *reinterpret_cast<const float2*>(nxt + 8 * 128 + col0);
                xf0[kb][2] = *reinterpret_cast<const float2*>(nxt + col0 + 8);
                xf0[kb][3] = *reinterpret_cast<const float2*>(nxt + 8 * 128 + col0 + 8);
            }
        }

        // ---- GEMM1 on half1 ----
        #pragma unroll
        for (int kb = 0; kb < 4; kb++) {
            s1 += fabsf(xf1[kb][0].x) + fabsf(xf1[kb][0].y) + fabsf(xf1[kb][2].x) + fabsf(xf1[kb][2].y);
            s2 += fabsf(xf1[kb][1].x) + fabsf(xf1[kb][1].y) + fabsf(xf1[kb][3].x) + fabsf(xf1[kb][3].y);
            u32 ah[4], al[4];
            #pragma unroll
            for (int j = 0; j < 4; j++) packhl(xf1[kb][j].x, xf1[kb][j].y, ah[j], al[j]);
            #pragma unroll
            for (int nbp = 0; nbp < 2; nbp++) {
                const u32 off = (u32)((nbp * 16 * XSTR + (4 + kb) * 16) * 2);
                u32 bh[4], bl[4];
                ldmx4(bh, w2h + off);
                ldmx4(bl, w2l + off);
                mmabf(accA[2*nbp],   ah, bh[0], bh[1]);
                mmabf(accB[2*nbp],   ah, bl[0], bl[1]);
                mmabf(accB[2*nbp],   al, bh[0], bh[1]);
                mmabf(accA[2*nbp+1], ah, bh[2], bh[3]);
                mmabf(accB[2*nbp+1], ah, bl[2], bl[3]);
                mmabf(accB[2*nbp+1], al, bh[2], bh[3]);
            }
        }

        // ---- mask ----
        s1 += __shfl_xor_sync(0xffffffffu, s1, 1); s1 += __shfl_xor_sync(0xffffffffu, s1, 2);
        s2 += __shfl_xor_sync(0xffffffffu, s2, 1); s2 += __shfl_xor_sync(0xffffffffu, s2, 2);
        const bool mr1 = s1 > 128.0f, mr2 = s2 > 128.0f;      // sum>128 <=> mean|x|>1
        const u32 bal1 = __ballot_sync(0xffffffffu, mr1);
        const u32 bal2 = __ballot_sync(0xffffffffu, mr2);

        // ---- epilogue1 in regs: bias+relu, re-split -> GEMM2 A-fragments ----
        u32 A2h[2][4], A2l[2][4];
        #pragma unroll
        for (int nb = 0; nb < 4; nb++) {
            float v0 = fmaxf(accA[nb][0] + accB[nb][0] + b2c[nb].x, 0.f);
            float v1 = fmaxf(accA[nb][1] + accB[nb][1] + b2c[nb].y, 0.f);
            float v2 = fmaxf(accA[nb][2] + accB[nb][2] + b2c[nb].x, 0.f);
            float v3 = fmaxf(accA[nb][3] + accB[nb][3] + b2c[nb].y, 0.f);
            const int kb2 = nb >> 1, base = (nb & 1) * 2;
            packhl(v0, v1, A2h[kb2][base + 0], A2l[kb2][base + 0]);
            packhl(v2, v3, A2h[kb2][base + 1], A2l[kb2][base + 1]);
        }

        // ---- GEMM2: out = o2 @ Wf^T (M=16,N=128,K=32), nh-split ----
        const long row1 = rw + q, row2 = rw + q + 8;
        #pragma unroll
        for (int nh = 0; nh < 2; nh++) {
            float acc2[8][4];
            #pragma unroll
            for (int nb = 0; nb < 8; nb++)
                #pragma unroll
                for (int j = 0; j < 4; j++) acc2[nb][j] = 0.f;
            #pragma unroll
            for (int kb2 = 0; kb2 < 2; kb2++)
                #pragma unroll
                for (int nbp = 0; nbp < 4; nbp++) {
                    const u32 off = (u32)(((nh * 64 + nbp * 16) * ASTR + kb2 * 16) * 2);
                    u32 bh4[4], bl4[4];
                    ldmx4(bh4, wfh + off);
                    ldmx4(bl4, wfl + off);
                    mmabf(acc2[2*nbp],   A2h[kb2], bh4[0], bh4[1]);
                    mmabf(acc2[2*nbp],   A2h[kb2], bl4[0], bl4[1]);
                    mmabf(acc2[2*nbp],   A2l[kb2], bh4[0], bh4[1]);
                    mmabf(acc2[2*nbp+1], A2h[kb2], bh4[2], bh4[3]);
                    mmabf(acc2[2*nbp+1], A2h[kb2], bl4[2], bl4[3]);
                    mmabf(acc2[2*nbp+1], A2l[kb2], bh4[2], bh4[3]);
                }
            #pragma unroll
            for (int nb = 0; nb < 8; nb++) {
                const int col = nh * 64 + nb * 8 + c2;
                const float2 bv = *reinterpret_cast<const float2*>(bfs + col);
                if (!mr1)
                    *reinterpret_cast<float2*>(out + row1 * 128 + col) =
                        make_float2(acc2[nb][0] + bv.x, acc2[nb][1] + bv.y);
                if (!mr2)
                    *reinterpret_cast<float2*>(out + row2 * 128 + col) =
                        make_float2(acc2[nb][2] + bv.x, acc2[nb][3] + bv.y);
            }
        }

        // ---- rare slow path: masked rows computed fully in fp32 ----
        if (bal1 | bal2) {
            float* o1s = scr + wid * 64;
            for (int r = 0; r < 16; r++) {
                const bool masked = (r < 8) ? ((bal1 >> (4 * r)) & 1u)
                                            : ((bal2 >> (4 * (r - 8))) & 1u);
                if (!masked) continue;
                const float4* xg4 = reinterpret_cast<const float4*>(X + (rw + r) * 128);
                #pragma unroll
                for (int uu = 0; uu < 2; uu++) {
                    const int u = lane + uu * 32;
                    const float4* wr = reinterpret_cast<const float4*>(W1 + u * 128);
                    float sacc = 0.f;
                    for (int k = 0; k < 32; k++) {
                        float4 a = xg4[k], w = wr[k];
                        sacc += a.x * w.x + a.y * w.y + a.z * w.z + a.w * w.w;
                    }
                    o1s[u] = fmaxf(sacc + b1[u], 0.f);
                }
                __syncwarp();
                #pragma unroll
                for (int jj = 0; jj < 4; jj++) {
                    const int d = lane + jj * 32;
                    const float* wf = Wf + d * 64;
                    float acc = bfs[d];
                    for (int u = 0; u < 64; u++) acc += o1s[u] * wf[u];
                    out[(rw + r) * 128 + d] = acc;
                }
                __syncwarp();
            }
        }
    }
}

extern "C" void kernel_launch(void* const* d_in, const int* in_sizes, int n_in,
                              void* d_out, int out_size)
{
    const float* X  = (const float*)d_in[0];
    const float* W1 = (const float*)d_in[1];
    const float* b1 = (const float*)d_in[2];
    const float* W2 = (const float*)d_in[3];
    const float* b2 = (const float*)d_in[4];
    const float* Wf = (const float*)d_in[5];
    const float* bf = (const float*)d_in[6];
    float* out = (float*)d_out;

    const int nrows = in_sizes[0] / 128;

    cudaFuncSetAttribute(dynlayer_mma,
                         cudaFuncAttributeMaxDynamicSharedMemorySize, SM_BYTES);
    int nsm = 148;
    cudaDeviceGetAttribute(&nsm, cudaDevAttrMultiProcessorCount, 0);

    dynlayer_mma<<<2 * nsm, NTHREADS, SM_BYTES>>>(X, W1, b1, W2, b2, Wf, bf, out, nrows);
}

// round 13
// speedup vs baseline: 1.1723x; 1.1723x over previous
#include <cuda_runtime.h>
#include <cuda_fp16.h>
#include <cstdint>

#define NTHREADS 256

// ---- smem: fp16 weights (hi only) ----
#define XSTR  136                      // W2 row stride (fp16 elems)
#define ASTR  72                       // Wf row stride
#define O_W2H 0
#define O_WFH (32 * XSTR)
#define SM_ELEMS (O_WFH + 128 * ASTR)
#define O_BIAS (SM_ELEMS * 2)          // bytes: b2[32]f32 then bf[128]f32
#define O_SCR  (O_BIAS + 4 * (32 + 128))
#define SM_BYTES (O_SCR + 8 * 64 * 4)  // + per-warp o1 scratch (slow path)

typedef unsigned u32;

static __device__ __forceinline__ u32 s2u(const void* p) {
    u32 a;
    asm("{ .reg .u64 t; cvta.to.shared.u64 t, %1; cvt.u32.u64 %0, t; }" : "=r"(a) : "l"(p));
    return a;
}
// (a,b) -> packed f16x2 hi (RN, a in low half) + packed f16x2 lo (residual)
static __device__ __forceinline__ void packhl(float a, float b, u32& h, u32& l) {
    __half2 hh = __floats2half2_rn(a, b);        // x=a (lo), y=b (hi)
    h = *reinterpret_cast<u32*>(&hh);
    float2 bk = __half22float2(hh);
    __half2 ll = __floats2half2_rn(a - bk.x, b - bk.y);
    l = *reinterpret_cast<u32*>(&ll);
}
static __device__ __forceinline__ void ldmx4(u32 a[4], u32 addr) {
    asm volatile("ldmatrix.sync.aligned.m8n8.x4.shared.b16 {%0,%1,%2,%3}, [%4];"
                 : "=r"(a[0]), "=r"(a[1]), "=r"(a[2]), "=r"(a[3]) : "r"(addr));
}
static __device__ __forceinline__ void mmaf16(float c[4], const u32 a[4], u32 b0, u32 b1) {
    asm volatile("mma.sync.aligned.m16n8k16.row.col.f32.f16.f16.f32 "
                 "{%0,%1,%2,%3}, {%4,%5,%6,%7}, {%8,%9}, {%0,%1,%2,%3};"
                 : "+f"(c[0]), "+f"(c[1]), "+f"(c[2]), "+f"(c[3])
                 : "r"(a[0]), "r"(a[1]), "r"(a[2]), "r"(a[3]), "r"(b0), "r"(b1));
}

__global__ void __launch_bounds__(NTHREADS, 2)
dynlayer_mma(const float* __restrict__ X,  const float* __restrict__ W1,
             const float* __restrict__ b1, const float* __restrict__ W2,
             const float* __restrict__ b2, const float* __restrict__ Wf,
             const float* __restrict__ bf, float* __restrict__ out, int nrows)
{
    extern __shared__ char smraw[];
    __half* sh = (__half*)smraw;
    float* b2s = (float*)(smraw + O_BIAS);
    float* bfs = b2s + 32;
    float* scr = (float*)(smraw + O_SCR);
    const u32 sb = s2u(smraw);
    const int tid = threadIdx.x, wid = tid >> 5, lane = tid & 31;

    // ---- stage fp16-hi weights (padded row-major) + biases ----
    for (int i = tid; i < 32 * 128; i += NTHREADS) {
        int u = i >> 7, k = i & 127;
        sh[O_W2H + u * XSTR + k] = __float2half_rn(W2[i]);
    }
    for (int i = tid; i < 128 * 64; i += NTHREADS) {
        int n = i >> 6, k = i & 63;
        sh[O_WFH + n * ASTR + k] = __float2half_rn(Wf[i]);
    }
    if (tid < 32)  b2s[tid] = b2[tid];
    if (tid < 128) bfs[tid] = bf[tid];
    __syncthreads();

    const int q  = lane >> 2;          // row-in-group 0..7
    const int c2 = (lane & 3) * 2;     // k/col pair base

    const int brow  = ((lane >> 4) & 1) * 8 + (lane & 7);
    const int bcolh = ((lane >> 3) & 1) * 8;
    const u32 w2h = sb + (u32)((O_W2H + brow * XSTR + bcolh) * 2);
    const u32 wfh = sb + (u32)((O_WFH + brow * ASTR + bcolh) * 2);

    float2 b2c[4];
    #pragma unroll
    for (int nb = 0; nb < 4; nb++)
        b2c[nb] = *reinterpret_cast<const float2*>(b2s + nb * 8 + c2);

    const int ntiles = nrows >> 7;     // 128 rows/CTA-tile, 16 per warp
    for (int t = blockIdx.x; t < ntiles; t += gridDim.x) {
        const long rw = ((long)t << 7) + wid * 16;
        const float* xr0 = X + (rw + q) * 128;
        const float* xr1 = xr0 + 8 * 128;

        // L2 prefetch of next tile's slab
        if (t + gridDim.x < ntiles) {
            const char* p = (const char*)(X + (rw + (long)gridDim.x * 128) * 128) + lane * 256;
            asm volatile("prefetch.global.L2 [%0];" :: "l"(p));
        }

        float s1 = 0.f, s2 = 0.f;
        float accA[4][4], accB[4][4];
        #pragma unroll
        for (int nb = 0; nb < 4; nb++)
            #pragma unroll
            for (int j = 0; j < 4; j++) { accA[nb][j] = 0.f; accB[nb][j] = 0.f; }

        // ---- GEMM1: o2 = x @ W2^T (M=16,N=32,K=128); 2-term fp16 (hh + lh) ----
        #pragma unroll
        for (int half = 0; half < 2; half++) {
            float2 xf[4][4];
            #pragma unroll
            for (int kb = 0; kb < 4; kb++) {
                const int col0 = (half * 4 + kb) * 16 + c2;
                xf[kb][0] = *reinterpret_cast<const float2*>(xr0 + col0);
                xf[kb][1] = *reinterpret_cast<const float2*>(xr1 + col0);
                xf[kb][2] = *reinterpret_cast<const float2*>(xr0 + col0 + 8);
                xf[kb][3] = *reinterpret_cast<const float2*>(xr1 + col0 + 8);
            }
            #pragma unroll
            for (int kb = 0; kb < 4; kb++) {
                s1 += fabsf(xf[kb][0].x) + fabsf(xf[kb][0].y) + fabsf(xf[kb][2].x) + fabsf(xf[kb][2].y);
                s2 += fabsf(xf[kb][1].x) + fabsf(xf[kb][1].y) + fabsf(xf[kb][3].x) + fabsf(xf[kb][3].y);
            }
            #pragma unroll
            for (int kb = 0; kb < 4; kb++) {
                u32 ah[4], al[4];
                #pragma unroll
                for (int j = 0; j < 4; j++) packhl(xf[kb][j].x, xf[kb][j].y, ah[j], al[j]);
                const int kg = half * 4 + kb;
                #pragma unroll
                for (int nbp = 0; nbp < 2; nbp++) {
                    const u32 off = (u32)((nbp * 16 * XSTR + kg * 16) * 2);
                    u32 bh[4];
                    ldmx4(bh, w2h + off);
                    mmaf16(accA[2*nbp],   ah, bh[0], bh[1]);
                    mmaf16(accB[2*nbp],   al, bh[0], bh[1]);
                    mmaf16(accA[2*nbp+1], ah, bh[2], bh[3]);
                    mmaf16(accB[2*nbp+1], al, bh[2], bh[3]);
                }
            }
        }

        // ---- mask: quad-reduce per-row sum|x| ----
        s1 += __shfl_xor_sync(0xffffffffu, s1, 1); s1 += __shfl_xor_sync(0xffffffffu, s1, 2);
        s2 += __shfl_xor_sync(0xffffffffu, s2, 1); s2 += __shfl_xor_sync(0xffffffffu, s2, 2);
        const bool mr1 = s1 > 128.0f, mr2 = s2 > 128.0f;      // sum>128 <=> mean|x|>1
        const u32 bal1 = __ballot_sync(0xffffffffu, mr1);
        const u32 bal2 = __ballot_sync(0xffffffffu, mr2);

        // ---- epilogue1 in regs: bias+relu, re-split -> GEMM2 A-fragments ----
        u32 A2h[2][4], A2l[2][4];
        #pragma unroll
        for (int nb = 0; nb < 4; nb++) {
            float v0 = fmaxf(accA[nb][0] + accB[nb][0] + b2c[nb].x, 0.f);
            float v1 = fmaxf(accA[nb][1] + accB[nb][1] + b2c[nb].y, 0.f);
            float v2 = fmaxf(accA[nb][2] + accB[nb][2] + b2c[nb].x, 0.f);
            float v3 = fmaxf(accA[nb][3] + accB[nb][3] + b2c[nb].y, 0.f);
            const int kb2 = nb >> 1, base = (nb & 1) * 2;     // C layout == A layout
            packhl(v0, v1, A2h[kb2][base + 0], A2l[kb2][base + 0]);
            packhl(v2, v3, A2h[kb2][base + 1], A2l[kb2][base + 1]);
        }

        // ---- GEMM2: out = o2 @ Wf^T (M=16,N=128,K=32), nh-split ----
        const long row1 = rw + q, row2 = rw + q + 8;
        #pragma unroll
        for (int nh = 0; nh < 2; nh++) {
            float acc2[8][4];
            #pragma unroll
            for (int nb = 0; nb < 8; nb++)
                #pragma unroll
                for (int j = 0; j < 4; j++) acc2[nb][j] = 0.f;
            #pragma unroll
            for (int kb2 = 0; kb2 < 2; kb2++)
                #pragma unroll
                for (int nbp = 0; nbp < 4; nbp++) {
                    const u32 off = (u32)(((nh * 64 + nbp * 16) * ASTR + kb2 * 16) * 2);
                    u32 bh4[4];
                    ldmx4(bh4, wfh + off);
                    mmaf16(acc2[2*nbp],   A2h[kb2], bh4[0], bh4[1]);
                    mmaf16(acc2[2*nbp],   A2l[kb2], bh4[0], bh4[1]);
                    mmaf16(acc2[2*nbp+1], A2h[kb2], bh4[2], bh4[3]);
                    mmaf16(acc2[2*nbp+1], A2l[kb2], bh4[2], bh4[3]);
                }
            #pragma unroll
            for (int nb = 0; nb < 8; nb++) {
                const int col = nh * 64 + nb * 8 + c2;
                const float2 bv = *reinterpret_cast<const float2*>(bfs + col);
                if (!mr1)
                    *reinterpret_cast<float2*>(out + row1 * 128 + col) =
                        make_float2(acc2[nb][0] + bv.x, acc2[nb][1] + bv.y);
                if (!mr2)
                    *reinterpret_cast<float2*>(out + row2 * 128 + col) =
                        make_float2(acc2[nb][2] + bv.x, acc2[nb][3] + bv.y);
            }
        }

        // ---- rare slow path: masked rows computed fully in fp32 ----
        if (bal1 | bal2) {
            float* o1s = scr + wid * 64;
            for (int r = 0; r < 16; r++) {
                const bool masked = (r < 8) ? ((bal1 >> (4 * r)) & 1u)
                                            : ((bal2 >> (4 * (r - 8))) & 1u);
                if (!masked) continue;
                const float4* xg4 = reinterpret_cast<const float4*>(X + (rw + r) * 128);
                #pragma unroll
                for (int uu = 0; uu < 2; uu++) {
                    const int u = lane + uu * 32;
                    const float4* wr = reinterpret_cast<const float4*>(W1 + u * 128);
                    float sacc = 0.f;
                    for (int k = 0; k < 32; k++) {
                        float4 a = xg4[k], w = wr[k];
                        sacc += a.x * w.x + a.y * w.y + a.z * w.z + a.w * w.w;
                    }
                    o1s[u] = fmaxf(sacc + b1[u], 0.f);
                }
                __syncwarp();
                #pragma unroll
                for (int jj = 0; jj < 4; jj++) {
                    const int d = lane + jj * 32;
                    const float* wf = Wf + d * 64;
                    float acc = bfs[d];
                    for (int u = 0; u < 64; u++) acc += o1s[u] * wf[u];
                    out[(rw + r) * 128 + d] = acc;
                }
                __syncwarp();
            }
        }
    }
}

extern "C" void kernel_launch(void* const* d_in, const int* in_sizes, int n_in,
                              void* d_out, int out_size)
{
    const float* X  = (const float*)d_in[0];
    const float* W1 = (const float*)d_in[1];
    const float* b1 = (const float*)d_in[2];
    const float* W2 = (const float*)d_in[3];
    const float* b2 = (const float*)d_in[4];
    const float* Wf = (const float*)d_in[5];
    const float* bf = (const float*)d_in[6];
    float* out = (float*)d_out;

    const int nrows = in_sizes[0] / 128;

    cudaFuncSetAttribute(dynlayer_mma,
                         cudaFuncAttributeMaxDynamicSharedMemorySize, SM_BYTES);
    int nsm = 148;
    cudaDeviceGetAttribute(&nsm, cudaDevAttrMultiProcessorCount, 0);

    dynlayer_mma<<<2 * nsm, NTHREADS, SM_BYTES>>>(X, W1, b1, W2, b2, Wf, bf, out, nrows);
}

// round 14
// speedup vs baseline: 1.1816x; 1.0080x over previous
#include <cuda_runtime.h>
#include <cuda_fp16.h>
#include <cstdint>

#define NTHREADS 256

// ---- smem: fp16 weights (hi only) ----
#define XSTR  136                      // W2 row stride (fp16 elems)
#define ASTR  72                       // Wf row stride
#define O_W2H 0
#define O_WFH (32 * XSTR)
#define SM_ELEMS (O_WFH + 128 * ASTR)
#define O_BIAS (SM_ELEMS * 2)          // bytes: b2[32]f32 then bf[128]f32
#define O_SCR  (O_BIAS + 4 * (32 + 128))
#define SM_BYTES (O_SCR + 8 * 64 * 4)  // + per-warp o1 scratch (slow path)

typedef unsigned u32;

static __device__ __forceinline__ u32 s2u(const void* p) {
    u32 a;
    asm("{ .reg .u64 t; cvta.to.shared.u64 t, %1; cvt.u32.u64 %0, t; }" : "=r"(a) : "l"(p));
    return a;
}
// (a,b) -> packed f16x2 hi (RN, a in low half) + packed f16x2 lo (residual)
static __device__ __forceinline__ void packhl(float a, float b, u32& h, u32& l) {
    __half2 hh = __floats2half2_rn(a, b);
    h = *reinterpret_cast<u32*>(&hh);
    float2 bk = __half22float2(hh);
    __half2 ll = __floats2half2_rn(a - bk.x, b - bk.y);
    l = *reinterpret_cast<u32*>(&ll);
}
static __device__ __forceinline__ void ldmx4(u32 a[4], u32 addr) {
    asm volatile("ldmatrix.sync.aligned.m8n8.x4.shared.b16 {%0,%1,%2,%3}, [%4];"
                 : "=r"(a[0]), "=r"(a[1]), "=r"(a[2]), "=r"(a[3]) : "r"(addr));
}
static __device__ __forceinline__ void mmaf16(float c[4], const u32 a[4], u32 b0, u32 b1) {
    asm volatile("mma.sync.aligned.m16n8k16.row.col.f32.f16.f16.f32 "
                 "{%0,%1,%2,%3}, {%4,%5,%6,%7}, {%8,%9}, {%0,%1,%2,%3};"
                 : "+f"(c[0]), "+f"(c[1]), "+f"(c[2]), "+f"(c[3])
                 : "r"(a[0]), "r"(a[1]), "r"(a[2]), "r"(a[3]), "r"(b0), "r"(b1));
}

__global__ void __launch_bounds__(NTHREADS, 2)
dynlayer_mma(const float* __restrict__ X,  const float* __restrict__ W1,
             const float* __restrict__ b1, const float* __restrict__ W2,
             const float* __restrict__ b2, const float* __restrict__ Wf,
             const float* __restrict__ bf, float* __restrict__ out, int nrows)
{
    extern __shared__ char smraw[];
    __half* sh = (__half*)smraw;
    float* b2s = (float*)(smraw + O_BIAS);
    float* bfs = b2s + 32;
    float* scr = (float*)(smraw + O_SCR);
    const u32 sb = s2u(smraw);
    const int tid = threadIdx.x, wid = tid >> 5, lane = tid & 31;

    // ---- stage weights + biases ----
    // W2's k-dim is stored PERMUTED within each 16-col block:
    //   physical p = 4j+r  ->  logical 2j+r (r<2), 2j+8+(r-2) (r>=2)
    // so a single per-lane float4 x load yields mma A-fragment pairs directly.
    for (int i = tid; i < 32 * 128; i += NTHREADS) {
        int u = i >> 7, k = i & 127;
        int kb = k >> 4, p = k & 15, j = p >> 2, r = p & 3;
        int l = (r < 2) ? (2 * j + r) : (2 * j + 8 + r - 2);
        sh[O_W2H + u * XSTR + kb * 16 + l] = __float2half_rn(W2[i]);
    }
    for (int i = tid; i < 128 * 64; i += NTHREADS) {
        int n = i >> 6, k = i & 63;
        sh[O_WFH + n * ASTR + k] = __float2half_rn(Wf[i]);
    }
    if (tid < 32)  b2s[tid] = b2[tid];
    if (tid < 128) bfs[tid] = bf[tid];
    __syncthreads();

    const int q  = lane >> 2;          // row-in-group 0..7
    const int c2 = (lane & 3) * 2;     // out-col pair base (C/A fragment)
    const int c4 = (lane & 3) * 4;     // x float4 col base (permuted-k A load)

    const int brow  = ((lane >> 4) & 1) * 8 + (lane & 7);
    const int bcolh = ((lane >> 3) & 1) * 8;
    const u32 w2h = sb + (u32)((O_W2H + brow * XSTR + bcolh) * 2);
    const u32 wfh = sb + (u32)((O_WFH + brow * ASTR + bcolh) * 2);

    float2 b2c[4];
    #pragma unroll
    for (int nb = 0; nb < 4; nb++)
        b2c[nb] = *reinterpret_cast<const float2*>(b2s + nb * 8 + c2);

    const int ntiles = nrows >> 7;     // 128 rows/CTA-tile, 16 per warp
    for (int t = blockIdx.x; t < ntiles; t += gridDim.x) {
        const long rw = ((long)t << 7) + wid * 16;
        const float* xr0 = X + (rw + q) * 128 + c4;        // row q
        const float* xr1 = xr0 + 8 * 128;                  // row q+8

        // L2 prefetch of next tile's slab
        if (t + gridDim.x < ntiles) {
            const char* p = (const char*)(X + (rw + (long)gridDim.x * 128) * 128) + lane * 256;
            asm volatile("prefetch.global.L2 [%0];" :: "l"(p));
        }

        float s1 = 0.f, s2 = 0.f;
        float accA[4][4], accB[4][4];
        #pragma unroll
        for (int nb = 0; nb < 4; nb++)
            #pragma unroll
            for (int j = 0; j < 4; j++) { accA[nb][j] = 0.f; accB[nb][j] = 0.f; }

        // ---- GEMM1: o2 = x @ W2^T (M=16,N=32,K=128); 2-term fp16, LDG.128 A ----
        #pragma unroll
        for (int half = 0; half < 2; half++) {
            float4 xq[4], xp[4];
            #pragma unroll
            for (int kb = 0; kb < 4; kb++) {               // 8 LDG.128, batched
                const int col0 = (half * 4 + kb) * 16;
                xq[kb] = *reinterpret_cast<const float4*>(xr0 + col0);
                xp[kb] = *reinterpret_cast<const float4*>(xr1 + col0);
            }
            #pragma unroll
            for (int kb = 0; kb < 4; kb++) {
                s1 += fabsf(xq[kb].x) + fabsf(xq[kb].y) + fabsf(xq[kb].z) + fabsf(xq[kb].w);
                s2 += fabsf(xp[kb].x) + fabsf(xp[kb].y) + fabsf(xp[kb].z) + fabsf(xp[kb].w);
            }
            #pragma unroll
            for (int kb = 0; kb < 4; kb++) {
                u32 ah[4], al[4];
                packhl(xq[kb].x, xq[kb].y, ah[0], al[0]);  // row q,   klow pair
                packhl(xp[kb].x, xp[kb].y, ah[1], al[1]);  // row q+8, klow pair
                packhl(xq[kb].z, xq[kb].w, ah[2], al[2]);  // row q,   khigh pair
                packhl(xp[kb].z, xp[kb].w, ah[3], al[3]);  // row q+8, khigh pair
                const int kg = half * 4 + kb;
                #pragma unroll
                for (int nbp = 0; nbp < 2; nbp++) {
                    const u32 off = (u32)((nbp * 16 * XSTR + kg * 16) * 2);
                    u32 bh[4];
                    ldmx4(bh, w2h + off);
                    mmaf16(accA[2*nbp],   ah, bh[0], bh[1]);
                    mmaf16(accB[2*nbp],   al, bh[0], bh[1]);
                    mmaf16(accA[2*nbp+1], ah, bh[2], bh[3]);
                    mmaf16(accB[2*nbp+1], al, bh[2], bh[3]);
                }
            }
        }

        // ---- mask: quad-reduce per-row sum|x| ----
        s1 += __shfl_xor_sync(0xffffffffu, s1, 1); s1 += __shfl_xor_sync(0xffffffffu, s1, 2);
        s2 += __shfl_xor_sync(0xffffffffu, s2, 1); s2 += __shfl_xor_sync(0xffffffffu, s2, 2);
        const bool mr1 = s1 > 128.0f, mr2 = s2 > 128.0f;      // sum>128 <=> mean|x|>1
        const u32 bal1 = __ballot_sync(0xffffffffu, mr1);
        const u32 bal2 = __ballot_sync(0xffffffffu, mr2);

        // ---- epilogue1 in regs: bias+relu, re-split -> GEMM2 A-fragments ----
        u32 A2h[2][4], A2l[2][4];
        #pragma unroll
        for (int nb = 0; nb < 4; nb++) {
            float v0 = fmaxf(accA[nb][0] + accB[nb][0] + b2c[nb].x, 0.f);
            float v1 = fmaxf(accA[nb][1] + accB[nb][1] + b2c[nb].y, 0.f);
            float v2 = fmaxf(accA[nb][2] + accB[nb][2] + b2c[nb].x, 0.f);
            float v3 = fmaxf(accA[nb][3] + accB[nb][3] + b2c[nb].y, 0.f);
            const int kb2 = nb >> 1, base = (nb & 1) * 2;     // C layout == A layout
            packhl(v0, v1, A2h[kb2][base + 0], A2l[kb2][base + 0]);
            packhl(v2, v3, A2h[kb2][base + 1], A2l[kb2][base + 1]);
        }

        // ---- GEMM2: out = o2 @ Wf^T (M=16,N=128,K=32), nh-split ----
        const long row1 = rw + q, row2 = rw + q + 8;
        #pragma unroll
        for (int nh = 0; nh < 2; nh++) {
            float acc2[8][4];
            #pragma unroll
            for (int nb = 0; nb < 8; nb++)
                #pragma unroll
                for (int j = 0; j < 4; j++) acc2[nb][j] = 0.f;
            #pragma unroll
            for (int kb2 = 0; kb2 < 2; kb2++)
                #pragma unroll
                for (int nbp = 0; nbp < 4; nbp++) {
                    const u32 off = (u32)(((nh * 64 + nbp * 16) * ASTR + kb2 * 16) * 2);
                    u32 bh4[4];
                    ldmx4(bh4, wfh + off);
                    mmaf16(acc2[2*nbp],   A2h[kb2], bh4[0], bh4[1]);
                    mmaf16(acc2[2*nbp],   A2l[kb2], bh4[0], bh4[1]);
                    mmaf16(acc2[2*nbp+1], A2h[kb2], bh4[2], bh4[3]);
                    mmaf16(acc2[2*nbp+1], A2l[kb2], bh4[2], bh4[3]);
                }
            #pragma unroll
            for (int nb = 0; nb < 8; nb++) {
                const int col = nh * 64 + nb * 8 + c2;
                const float2 bv = *reinterpret_cast<const float2*>(bfs + col);
                if (!mr1)
                    *reinterpret_cast<float2*>(out + row1 * 128 + col) =
                        make_float2(acc2[nb][0] + bv.x, acc2[nb][1] + bv.y);
                if (!mr2)
                    *reinterpret_cast<float2*>(out + row2 * 128 + col) =
                        make_float2(acc2[nb][2] + bv.x, acc2[nb][3] + bv.y);
            }
        }

        // ---- rare slow path: masked rows computed fully in fp32 ----
        if (bal1 | bal2) {
            float* o1s = scr + wid * 64;
            for (int r = 0; r < 16; r++) {
                const bool masked = (r < 8) ? ((bal1 >> (4 * r)) & 1u)
                                            : ((bal2 >> (4 * (r - 8))) & 1u);
                if (!masked) continue;
                const float4* xg4 = reinterpret_cast<const float4*>(X + (rw + r) * 128);
                #pragma unroll
                for (int uu = 0; uu < 2; uu++) {
                    const int u = lane + uu * 32;
                    const float4* wr = reinterpret_cast<const float4*>(W1 + u * 128);
                    float sacc = 0.f;
                    for (int k = 0; k < 32; k++) {
                        float4 a = xg4[k], w = wr[k];
                        sacc += a.x * w.x + a.y * w.y + a.z * w.z + a.w * w.w;
                    }
                    o1s[u] = fmaxf(sacc + b1[u], 0.f);
                }
                __syncwarp();
                #pragma unroll
                for (int jj = 0; jj < 4; jj++) {
                    const int d = lane + jj * 32;
                    const float* wf = Wf + d * 64;
                    float acc = bfs[d];
                    for (int u = 0; u < 64; u++) acc += o1s[u] * wf[u];
                    out[(rw + r) * 128 + d] = acc;
                }
                __syncwarp();
            }
        }
    }
}

extern "C" void kernel_launch(void* const* d_in, const int* in_sizes, int n_in,
                              void* d_out, int out_size)
{
    const float* X  = (const float*)d_in[0];
    const float* W1 = (const float*)d_in[1];
    const float* b1 = (const float*)d_in[2];
    const float* W2 = (const float*)d_in[3];
    const float* b2 = (const float*)d_in[4];
    const float* Wf = (const float*)d_in[5];
    const float* bf = (const float*)d_in[6];
    float* out = (float*)d_out;

    const int nrows = in_sizes[0] / 128;

    cudaFuncSetAttribute(dynlayer_mma,
                         cudaFuncAttributeMaxDynamicSharedMemorySize, SM_BYTES);
    int nsm = 148;
    cudaDeviceGetAttribute(&nsm, cudaDevAttrMultiProcessorCount, 0);

    dynlayer_mma<<<2 * nsm, NTHREADS, SM_BYTES>>>(X, W1, b1, W2, b2, Wf, bf, out, nrows);
}

// round 15
// speedup vs baseline: 1.2142x; 1.0276x over previous
#include <cuda_runtime.h>
#include <cuda_fp16.h>
#include <cstdint>

#define NTHREADS 256

// ---- smem: fp16 weights (hi only) ----
#define XSTR  136                      // W2 row stride (fp16 elems)
#define ASTR  72                       // Wf row stride
#define O_W2H 0
#define O_WFH (32 * XSTR)
#define SM_ELEMS (O_WFH + 128 * ASTR)
#define O_BIAS (SM_ELEMS * 2)          // bytes: b2[32]f32 then bf[128]f32
#define O_SCR  (O_BIAS + 4 * (32 + 128))
#define SM_BYTES (O_SCR + 8 * 64 * 4)  // + per-warp o1 scratch (slow path)

typedef unsigned u32;

static __device__ __forceinline__ u32 s2u(const void* p) {
    u32 a;
    asm("{ .reg .u64 t; cvta.to.shared.u64 t, %1; cvt.u32.u64 %0, t; }" : "=r"(a) : "l"(p));
    return a;
}
// (a,b) -> packed f16x2 hi (RN, a in low half) + packed f16x2 lo (residual)
static __device__ __forceinline__ void packhl(float a, float b, u32& h, u32& l) {
    __half2 hh = __floats2half2_rn(a, b);
    h = *reinterpret_cast<u32*>(&hh);
    float2 bk = __half22float2(hh);
    __half2 ll = __floats2half2_rn(a - bk.x, b - bk.y);
    l = *reinterpret_cast<u32*>(&ll);
}
static __device__ __forceinline__ u32 packh(float a, float b) {
    __half2 hh = __floats2half2_rn(a, b);
    return *reinterpret_cast<u32*>(&hh);
}
static __device__ __forceinline__ void ldmx4(u32 a[4], u32 addr) {
    asm volatile("ldmatrix.sync.aligned.m8n8.x4.shared.b16 {%0,%1,%2,%3}, [%4];"
                 : "=r"(a[0]), "=r"(a[1]), "=r"(a[2]), "=r"(a[3]) : "r"(addr));
}
static __device__ __forceinline__ void mmaf16(float c[4], const u32 a[4], u32 b0, u32 b1) {
    asm volatile("mma.sync.aligned.m16n8k16.row.col.f32.f16.f16.f32 "
                 "{%0,%1,%2,%3}, {%4,%5,%6,%7}, {%8,%9}, {%0,%1,%2,%3};"
                 : "+f"(c[0]), "+f"(c[1]), "+f"(c[2]), "+f"(c[3])
                 : "r"(a[0]), "r"(a[1]), "r"(a[2]), "r"(a[3]), "r"(b0), "r"(b1));
}

__global__ void __launch_bounds__(NTHREADS, 2)
dynlayer_mma(const float* __restrict__ X,  const float* __restrict__ W1,
             const float* __restrict__ b1, const float* __restrict__ W2,
             const float* __restrict__ b2, const float* __restrict__ Wf,
             const float* __restrict__ bf, float* __restrict__ out, int nrows)
{
    extern __shared__ char smraw[];
    __half* sh = (__half*)smraw;
    float* b2s = (float*)(smraw + O_BIAS);
    float* bfs = b2s + 32;
    float* scr = (float*)(smraw + O_SCR);
    const u32 sb = s2u(smraw);
    const int tid = threadIdx.x, wid = tid >> 5, lane = tid & 31;

    // ---- stage weights + biases ----
    // W2's k-dim is stored PERMUTED within each 16-col block:
    //   physical p = 4j+r  ->  logical 2j+r (r<2), 2j+8+(r-2) (r>=2)
    // so a single per-lane float4 x load yields mma A-fragment pairs directly.
    for (int i = tid; i < 32 * 128; i += NTHREADS) {
        int u = i >> 7, k = i & 127;
        int kb = k >> 4, p = k & 15, j = p >> 2, r = p & 3;
        int l = (r < 2) ? (2 * j + r) : (2 * j + 8 + r - 2);
        sh[O_W2H + u * XSTR + kb * 16 + l] = __float2half_rn(W2[i]);
    }
    for (int i = tid; i < 128 * 64; i += NTHREADS) {
        int n = i >> 6, k = i & 63;
        sh[O_WFH + n * ASTR + k] = __float2half_rn(Wf[i]);
    }
    if (tid < 32)  b2s[tid] = b2[tid];
    if (tid < 128) bfs[tid] = bf[tid];
    __syncthreads();

    const int q  = lane >> 2;          // row-in-group 0..7
    const int c2 = (lane & 3) * 2;     // out-col pair base (C/A fragment)
    const int c4 = (lane & 3) * 4;     // x float4 col base (permuted-k A load)

    const int brow  = ((lane >> 4) & 1) * 8 + (lane & 7);
    const int bcolh = ((lane >> 3) & 1) * 8;
    const u32 w2h = sb + (u32)((O_W2H + brow * XSTR + bcolh) * 2);
    const u32 wfh = sb + (u32)((O_WFH + brow * ASTR + bcolh) * 2);

    float2 b2c[4];
    #pragma unroll
    for (int nb = 0; nb < 4; nb++)
        b2c[nb] = *reinterpret_cast<const float2*>(b2s + nb * 8 + c2);

    const int ntiles = nrows >> 7;     // 128 rows/CTA-tile, 16 per warp
    for (int t = blockIdx.x; t < ntiles; t += gridDim.x) {
        const long rw = ((long)t << 7) + wid * 16;
        const float* xr0 = X + (rw + q) * 128 + c4;        // row q
        const float* xr1 = xr0 + 8 * 128;                  // row q+8

        // L2 prefetch of next tile's slab
        if (t + gridDim.x < ntiles) {
            const char* p = (const char*)(X + (rw + (long)gridDim.x * 128) * 128) + lane * 256;
            asm volatile("prefetch.global.L2 [%0];" :: "l"(p));
        }

        float s1 = 0.f, s2 = 0.f;
        float accA[4][4], accB[4][4];
        #pragma unroll
        for (int nb = 0; nb < 4; nb++)
            #pragma unroll
            for (int j = 0; j < 4; j++) { accA[nb][j] = 0.f; accB[nb][j] = 0.f; }

        // ---- GEMM1: o2 = x @ W2^T (M=16,N=32,K=128); 2-term fp16, LDG.128 A ----
        #pragma unroll
        for (int half = 0; half < 2; half++) {
            float4 xq[4], xp[4];
            #pragma unroll
            for (int kb = 0; kb < 4; kb++) {               // 8 LDG.128, batched
                const int col0 = (half * 4 + kb) * 16;
                xq[kb] = *reinterpret_cast<const float4*>(xr0 + col0);
                xp[kb] = *reinterpret_cast<const float4*>(xr1 + col0);
            }
            #pragma unroll
            for (int kb = 0; kb < 4; kb++) {
                s1 += fabsf(xq[kb].x) + fabsf(xq[kb].y) + fabsf(xq[kb].z) + fabsf(xq[kb].w);
                s2 += fabsf(xp[kb].x) + fabsf(xp[kb].y) + fabsf(xp[kb].z) + fabsf(xp[kb].w);
            }
            #pragma unroll
            for (int kb = 0; kb < 4; kb++) {
                u32 ah[4], al[4];
                packhl(xq[kb].x, xq[kb].y, ah[0], al[0]);  // row q,   klow pair
                packhl(xp[kb].x, xp[kb].y, ah[1], al[1]);  // row q+8, klow pair
                packhl(xq[kb].z, xq[kb].w, ah[2], al[2]);  // row q,   khigh pair
                packhl(xp[kb].z, xp[kb].w, ah[3], al[3]);  // row q+8, khigh pair
                const int kg = half * 4 + kb;
                #pragma unroll
                for (int nbp = 0; nbp < 2; nbp++) {
                    const u32 off = (u32)((nbp * 16 * XSTR + kg * 16) * 2);
                    u32 bh[4];
                    ldmx4(bh, w2h + off);
                    mmaf16(accA[2*nbp],   ah, bh[0], bh[1]);
                    mmaf16(accB[2*nbp],   al, bh[0], bh[1]);
                    mmaf16(accA[2*nbp+1], ah, bh[2], bh[3]);
                    mmaf16(accB[2*nbp+1], al, bh[2], bh[3]);
                }
            }
        }

        // ---- mask: quad-reduce per-row sum|x| (exact fp32 — do not weaken) ----
        s1 += __shfl_xor_sync(0xffffffffu, s1, 1); s1 += __shfl_xor_sync(0xffffffffu, s1, 2);
        s2 += __shfl_xor_sync(0xffffffffu, s2, 1); s2 += __shfl_xor_sync(0xffffffffu, s2, 2);
        const bool mr1 = s1 > 128.0f, mr2 = s2 > 128.0f;      // sum>128 <=> mean|x|>1
        const u32 bal1 = __ballot_sync(0xffffffffu, mr1);
        const u32 bal2 = __ballot_sync(0xffffffffu, mr2);

        // ---- epilogue1 in regs: bias+relu, fp16-hi only -> GEMM2 A-fragments ----
        u32 A2h[2][4];
        #pragma unroll
        for (int nb = 0; nb < 4; nb++) {
            float v0 = fmaxf(accA[nb][0] + accB[nb][0] + b2c[nb].x, 0.f);
            float v1 = fmaxf(accA[nb][1] + accB[nb][1] + b2c[nb].y, 0.f);
            float v2 = fmaxf(accA[nb][2] + accB[nb][2] + b2c[nb].x, 0.f);
            float v3 = fmaxf(accA[nb][3] + accB[nb][3] + b2c[nb].y, 0.f);
            const int kb2 = nb >> 1, base = (nb & 1) * 2;     // C layout == A layout
            A2h[kb2][base + 0] = packh(v0, v1);
            A2h[kb2][base + 1] = packh(v2, v3);
        }

        // ---- GEMM2: out = o2 @ Wf^T (M=16,N=128,K=32), hi-term only, nh-split ----
        const long row1 = rw + q, row2 = rw + q + 8;
        #pragma unroll
        for (int nh = 0; nh < 2; nh++) {
            float acc2[8][4];
            #pragma unroll
            for (int nb = 0; nb < 8; nb++)
                #pragma unroll
                for (int j = 0; j < 4; j++) acc2[nb][j] = 0.f;
            #pragma unroll
            for (int kb2 = 0; kb2 < 2; kb2++)
                #pragma unroll
                for (int nbp = 0; nbp < 4; nbp++) {
                    const u32 off = (u32)(((nh * 64 + nbp * 16) * ASTR + kb2 * 16) * 2);
                    u32 bh4[4];
                    ldmx4(bh4, wfh + off);
                    mmaf16(acc2[2*nbp],   A2h[kb2], bh4[0], bh4[1]);
                    mmaf16(acc2[2*nbp+1], A2h[kb2], bh4[2], bh4[3]);
                }
            #pragma unroll
            for (int nb = 0; nb < 8; nb++) {
                const int col = nh * 64 + nb * 8 + c2;
                const float2 bv = *reinterpret_cast<const float2*>(bfs + col);
                if (!mr1)
                    *reinterpret_cast<float2*>(out + row1 * 128 + col) =
                        make_float2(acc2[nb][0] + bv.x, acc2[nb][1] + bv.y);
                if (!mr2)
                    *reinterpret_cast<float2*>(out + row2 * 128 + col) =
                        make_float2(acc2[nb][2] + bv.x, acc2[nb][3] + bv.y);
            }
        }

        // ---- rare slow path: masked rows computed fully in fp32 ----
        if (bal1 | bal2) {
            float* o1s = scr + wid * 64;
            for (int r = 0; r < 16; r++) {
                const bool masked = (r < 8) ? ((bal1 >> (4 * r)) & 1u)
                                            : ((bal2 >> (4 * (r - 8))) & 1u);
                if (!masked) continue;
                const float4* xg4 = reinterpret_cast<const float4*>(X + (rw + r) * 128);
                #pragma unroll
                for (int uu = 0; uu < 2; uu++) {
                    const int u = lane + uu * 32;
                    const float4* wr = reinterpret_cast<const float4*>(W1 + u * 128);
                    float sacc = 0.f;
                    for (int k = 0; k < 32; k++) {
                        float4 a = xg4[k], w = wr[k];
                        sacc += a.x * w.x + a.y * w.y + a.z * w.z + a.w * w.w;
                    }
                    o1s[u] = fmaxf(sacc + b1[u], 0.f);
                }
                __syncwarp();
                #pragma unroll
                for (int jj = 0; jj < 4; jj++) {
                    const int d = lane + jj * 32;
                    const float* wf = Wf + d * 64;
                    float acc = bfs[d];
                    for (int u = 0; u < 64; u++) acc += o1s[u] * wf[u];
                    out[(rw + r) * 128 + d] = acc;
                }
                __syncwarp();
            }
        }
    }
}

extern "C" void kernel_launch(void* const* d_in, const int* in_sizes, int n_in,
                              void* d_out, int out_size)
{
    const float* X  = (const float*)d_in[0];
    const float* W1 = (const float*)d_in[1];
    const float* b1 = (const float*)d_in[2];
    const float* W2 = (const float*)d_in[3];
    const float* b2 = (const float*)d_in[4];
    const float* Wf = (const float*)d_in[5];
    const float* bf = (const float*)d_in[6];
    float* out = (float*)d_out;

    const int nrows = in_sizes[0] / 128;

    cudaFuncSetAttribute(dynlayer_mma,
                         cudaFuncAttributeMaxDynamicSharedMemorySize, SM_BYTES);
    int nsm = 148;
    cudaDeviceGetAttribute(&nsm, cudaDevAttrMultiProcessorCount, 0);

    dynlayer_mma<<<2 * nsm, NTHREADS, SM_BYTES>>>(X, W1, b1, W2, b2, Wf, bf, out, nrows);
}

// round 16
// speedup vs baseline: 1.3188x; 1.0861x over previous
#include <cuda_runtime.h>
#include <cuda_fp16.h>
#include <cstdint>

#define NTHREADS 384
#define NW 12

// ---- smem layout ----
#define XSTR 136                        // W2 row stride (fp16 elems), permuted-k
#define ASTR 72                         // Wf row stride
#define O_W2H 0
#define O_WFH (32 * XSTR)
#define SM_ELEMS (O_WFH + 128 * ASTR)   // 13568 fp16
#define O_BIAS (SM_ELEMS * 2)           // byte off: b2[32]f32 then bf[128]f32
#define O_STAGE 28672                   // 1KB-aligned; stages: 12 warps x 2 x 8KB
#define STAGE_BYTES 8192
#define O_SCR (O_STAGE + NW * 2 * STAGE_BYTES)   // 225280
#define SM_BYTES (O_SCR + NW * 64 * 4)           // 228352 <= 232448 (227KB cap)

typedef unsigned u32;

static __device__ __forceinline__ u32 s2u(const void* p) {
    u32 a;
    asm("{ .reg .u64 t; cvta.to.shared.u64 t, %1; cvt.u32.u64 %0, t; }" : "=r"(a) : "l"(p));
    return a;
}
static __device__ __forceinline__ void packhl(float a, float b, u32& h, u32& l) {
    __half2 hh = __floats2half2_rn(a, b);
    h = *reinterpret_cast<u32*>(&hh);
    float2 bk = __half22float2(hh);
    __half2 ll = __floats2half2_rn(a - bk.x, b - bk.y);
    l = *reinterpret_cast<u32*>(&ll);
}
static __device__ __forceinline__ u32 packh(float a, float b) {
    __half2 hh = __floats2half2_rn(a, b);
    return *reinterpret_cast<u32*>(&hh);
}
static __device__ __forceinline__ void ldmx4(u32 a[4], u32 addr) {
    asm volatile("ldmatrix.sync.aligned.m8n8.x4.shared.b16 {%0,%1,%2,%3}, [%4];"
                 : "=r"(a[0]), "=r"(a[1]), "=r"(a[2]), "=r"(a[3]) : "r"(addr));
}
static __device__ __forceinline__ float4 lds128(u32 addr) {
    float4 v;
    asm volatile("ld.shared.v4.f32 {%0,%1,%2,%3}, [%4];"
                 : "=f"(v.x), "=f"(v.y), "=f"(v.z), "=f"(v.w) : "r"(addr));
    return v;
}
static __device__ __forceinline__ void cp16(u32 dst, const void* src) {
    asm volatile("cp.async.cg.shared.global [%0], [%1], 16;" :: "r"(dst), "l"(src) : "memory");
}
#define CP_COMMIT() asm volatile("cp.async.commit_group;" ::: "memory")
#define CP_WAIT1()  asm volatile("cp.async.wait_group 1;"  ::: "memory")
#define CP_WAIT0()  asm volatile("cp.async.wait_group 0;"  ::: "memory")

static __device__ __forceinline__ void mmaf16(float c[4], const u32 a[4], u32 b0, u32 b1) {
    asm volatile("mma.sync.aligned.m16n8k16.row.col.f32.f16.f16.f32 "
                 "{%0,%1,%2,%3}, {%4,%5,%6,%7}, {%8,%9}, {%0,%1,%2,%3};"
                 : "+f"(c[0]), "+f"(c[1]), "+f"(c[2]), "+f"(c[3])
                 : "r"(a[0]), "r"(a[1]), "r"(a[2]), "r"(a[3]), "r"(b0), "r"(b1));
}

__global__ void __launch_bounds__(NTHREADS, 1)
dynlayer_mma(const float* __restrict__ X,  const float* __restrict__ W1,
             const float* __restrict__ b1, const float* __restrict__ W2,
             const float* __restrict__ b2, const float* __restrict__ Wf,
             const float* __restrict__ bf, float* __restrict__ out, int nrows)
{
    extern __shared__ char smraw[];
    __half* sh = (__half*)smraw;
    float* b2s = (float*)(smraw + O_BIAS);
    float* bfs = b2s + 32;
    float* scr = (float*)(smraw + O_SCR);
    const u32 sb = s2u(smraw);
    const int tid = threadIdx.x, wid = tid >> 5, lane = tid & 31;

    // ---- stage weights + biases (W2 k-permuted as in R13) ----
    for (int i = tid; i < 32 * 128; i += NTHREADS) {
        int u = i >> 7, k = i & 127;
        int kb = k >> 4, p = k & 15, j = p >> 2, r = p & 3;
        int l = (r < 2) ? (2 * j + r) : (2 * j + 8 + r - 2);
        sh[O_W2H + u * XSTR + kb * 16 + l] = __float2half_rn(W2[i]);
    }
    for (int i = tid; i < 128 * 64; i += NTHREADS) {
        int n = i >> 6, k = i & 63;
        sh[O_WFH + n * ASTR + k] = __float2half_rn(Wf[i]);
    }
    if (tid < 32)  b2s[tid] = b2[tid];
    if (tid < 128) bfs[tid] = bf[tid];
    __syncthreads();

    const int q  = lane >> 2;          // row-in-group 0..7
    const int c2 = (lane & 3) * 2;     // out-col pair base

    const int brow  = ((lane >> 4) & 1) * 8 + (lane & 7);
    const int bcolh = ((lane >> 3) & 1) * 8;
    const u32 w2h = sb + (u32)((O_W2H + brow * XSTR + bcolh) * 2);
    const u32 wfh = sb + (u32)((O_WFH + brow * ASTR + bcolh) * 2);

    float2 b2c[4];
    #pragma unroll
    for (int nb = 0; nb < 4; nb++)
        b2c[nb] = *reinterpret_cast<const float2*>(b2s + nb * 8 + c2);

    const u32 stage0 = sb + O_STAGE + (u32)(wid * 2) * STAGE_BYTES;
    // per-lane LDS base within a stage: row q, chunk (lane&3); rows q/q+8 share parity
    const u32 xoffA = (u32)(q * 512 + (lane & 3) * 16);
    const u32 hx64  = (u32)((q & 1) * 64);          // XOR term for this lane's rows

    const int NT = nrows >> 4;                      // 16-row warp-tiles
    const int GW = gridDim.x * NW;
    const int gw0 = blockIdx.x * NW + wid;

    // stage loader: row j, chunk = lane; dst chunk-swizzle: ^((j&1)*64)
    auto stage_load = [&](int buf, int tile) {
        const u32 sbase = stage0 + (u32)buf * STAGE_BYTES;
        const float* src = X + (long)tile * 16 * 128 + lane * 4;
        #pragma unroll
        for (int j = 0; j < 16; j++)
            cp16(sbase + (u32)(j * 512) + (((u32)lane * 16) ^ ((u32)(j & 1) * 64)),
                 src + j * 128);
    };

    // ---- prologue: two stages in flight ----
    if (gw0 < NT) stage_load(0, gw0);
    CP_COMMIT();
    if (gw0 + GW < NT) stage_load(1, gw0 + GW);
    CP_COMMIT();

    int buf = 0;
    for (int t = gw0; t < NT; t += GW, buf ^= 1) {
        CP_WAIT1();
        __syncwarp();
        const u32 xb0 = stage0 + (u32)buf * STAGE_BYTES + xoffA;
        const u32 xb1 = xb0 + 8 * 512;
        const long rw = (long)t * 16;

        float s1 = 0.f, s2 = 0.f;
        float accA[4][4], accB[4][4];
        #pragma unroll
        for (int nb = 0; nb < 4; nb++)
            #pragma unroll
            for (int j = 0; j < 4; j++) { accA[nb][j] = 0.f; accB[nb][j] = 0.f; }

        // ---- GEMM1: o2 = x @ W2^T (M=16,N=32,K=128); x from swizzled smem ----
        #pragma unroll
        for (int half = 0; half < 2; half++) {
            float4 xq[4], xp[4];
            #pragma unroll
            for (int kb = 0; kb < 4; kb++) {
                const u32 off = ((u32)((half * 4 + kb) * 64)) ^ hx64;
                xq[kb] = lds128(xb0 + off);
                xp[kb] = lds128(xb1 + off);
            }
            #pragma unroll
            for (int kb = 0; kb < 4; kb++) {
                s1 += fabsf(xq[kb].x) + fabsf(xq[kb].y) + fabsf(xq[kb].z) + fabsf(xq[kb].w);
                s2 += fabsf(xp[kb].x) + fabsf(xp[kb].y) + fabsf(xp[kb].z) + fabsf(xp[kb].w);
            }
            #pragma unroll
            for (int kb = 0; kb < 4; kb++) {
                u32 ah[4], al[4];
                packhl(xq[kb].x, xq[kb].y, ah[0], al[0]);
                packhl(xp[kb].x, xp[kb].y, ah[1], al[1]);
                packhl(xq[kb].z, xq[kb].w, ah[2], al[2]);
                packhl(xp[kb].z, xp[kb].w, ah[3], al[3]);
                const int kg = half * 4 + kb;
                #pragma unroll
                for (int nbp = 0; nbp < 2; nbp++) {
                    const u32 off = (u32)((nbp * 16 * XSTR + kg * 16) * 2);
                    u32 bh[4];
                    ldmx4(bh, w2h + off);
                    mmaf16(accA[2*nbp],   ah, bh[0], bh[1]);
                    mmaf16(accB[2*nbp],   al, bh[0], bh[1]);
                    mmaf16(accA[2*nbp+1], ah, bh[2], bh[3]);
                    mmaf16(accB[2*nbp+1], al, bh[2], bh[3]);
                }
            }
        }
        __syncwarp();   // all lanes done reading this stage
        if (t + 2 * GW < NT) stage_load(buf, t + 2 * GW);
        CP_COMMIT();    // always commit (possibly empty) to keep group count

        // ---- mask: quad-reduce per-row sum|x| (exact fp32) ----
        s1 += __shfl_xor_sync(0xffffffffu, s1, 1); s1 += __shfl_xor_sync(0xffffffffu, s1, 2);
        s2 += __shfl_xor_sync(0xffffffffu, s2, 1); s2 += __shfl_xor_sync(0xffffffffu, s2, 2);
        const bool mr1 = s1 > 128.0f, mr2 = s2 > 128.0f;      // sum>128 <=> mean|x|>1
        const u32 bal1 = __ballot_sync(0xffffffffu, mr1);
        const u32 bal2 = __ballot_sync(0xffffffffu, mr2);

        // ---- epilogue1 in regs: bias+relu -> GEMM2 A-fragments (hi only) ----
        u32 A2h[2][4];
        #pragma unroll
        for (int nb = 0; nb < 4; nb++) {
            float v0 = fmaxf(accA[nb][0] + accB[nb][0] + b2c[nb].x, 0.f);
            float v1 = fmaxf(accA[nb][1] + accB[nb][1] + b2c[nb].y, 0.f);
            float v2 = fmaxf(accA[nb][2] + accB[nb][2] + b2c[nb].x, 0.f);
            float v3 = fmaxf(accA[nb][3] + accB[nb][3] + b2c[nb].y, 0.f);
            const int kb2 = nb >> 1, base = (nb & 1) * 2;
            A2h[kb2][base + 0] = packh(v0, v1);
            A2h[kb2][base + 1] = packh(v2, v3);
        }

        // ---- GEMM2: out = o2 @ Wf^T (M=16,N=128,K=32), nh-split ----
        const long row1 = rw + q, row2 = rw + q + 8;
        #pragma unroll
        for (int nh = 0; nh < 2; nh++) {
            float acc2[8][4];
            #pragma unroll
            for (int nb = 0; nb < 8; nb++)
                #pragma unroll
                for (int j = 0; j < 4; j++) acc2[nb][j] = 0.f;
            #pragma unroll
            for (int kb2 = 0; kb2 < 2; kb2++)
                #pragma unroll
                for (int nbp = 0; nbp < 4; nbp++) {
                    const u32 off = (u32)(((nh * 64 + nbp * 16) * ASTR + kb2 * 16) * 2);
                    u32 bh4[4];
                    ldmx4(bh4, wfh + off);
                    mmaf16(acc2[2*nbp],   A2h[kb2], bh4[0], bh4[1]);
                    mmaf16(acc2[2*nbp+1], A2h[kb2], bh4[2], bh4[3]);
                }
            #pragma unroll
            for (int nb = 0; nb < 8; nb++) {
                const int col = nh * 64 + nb * 8 + c2;
                const float2 bv = *reinterpret_cast<const float2*>(bfs + col);
                if (!mr1)
                    *reinterpret_cast<float2*>(out + row1 * 128 + col) =
                        make_float2(acc2[nb][0] + bv.x, acc2[nb][1] + bv.y);
                if (!mr2)
                    *reinterpret_cast<float2*>(out + row2 * 128 + col) =
                        make_float2(acc2[nb][2] + bv.x, acc2[nb][3] + bv.y);
            }
        }

        // ---- rare slow path: masked rows computed fully in fp32 from global ----
        if (bal1 | bal2) {
            float* o1s = scr + wid * 64;
            for (int r = 0; r < 16; r++) {
                const bool masked = (r < 8) ? ((bal1 >> (4 * r)) & 1u)
                                            : ((bal2 >> (4 * (r - 8))) & 1u);
                if (!masked) continue;
                const float4* xg4 = reinterpret_cast<const float4*>(X + (rw + r) * 128);
                #pragma unroll
                for (int uu = 0; uu < 2; uu++) {
                    const int u = lane + uu * 32;
                    const float4* wr = reinterpret_cast<const float4*>(W1 + u * 128);
                    float sacc = 0.f;
                    for (int k = 0; k < 32; k++) {
                        float4 a = xg4[k], w = wr[k];
                        sacc += a.x * w.x + a.y * w.y + a.z * w.z + a.w * w.w;
                    }
                    o1s[u] = fmaxf(sacc + b1[u], 0.f);
                }
                __syncwarp();
                #pragma unroll
                for (int jj = 0; jj < 4; jj++) {
                    const int d = lane + jj * 32;
                    const float* wf = Wf + d * 64;
                    float acc = bfs[d];
                    for (int u = 0; u < 64; u++) acc += o1s[u] * wf[u];
                    out[(rw + r) * 128 + d] = acc;
                }
                __syncwarp();
            }
        }
    }
    CP_WAIT0();
}

extern "C" void kernel_launch(void* const* d_in, const int* in_sizes, int n_in,
                              void* d_out, int out_size)
{
    const float* X  = (const float*)d_in[0];
    const float* W1 = (const float*)d_in[1];
    const float* b1 = (const float*)d_in[2];
    const float* W2 = (const float*)d_in[3];
    const float* b2 = (const float*)d_in[4];
    const float* Wf = (const float*)d_in[5];
    const float* bf = (const float*)d_in[6];
    float* out = (float*)d_out;

    const int nrows = in_sizes[0] / 128;

    cudaFuncSetAttribute(dynlayer_mma,
                         cudaFuncAttributeMaxDynamicSharedMemorySize, SM_BYTES);
    int nsm = 148;
    cudaDeviceGetAttribute(&nsm, cudaDevAttrMultiProcessorCount, 0);

    dynlayer_mma<<<nsm, NTHREADS, SM_BYTES>>>(X, W1, b1, W2, b2, Wf, bf, out, nrows);
}